// round 10
// baseline (speedup 1.0000x reference)
#include <cuda_runtime.h>
#include <cuda_bf16.h>
#include <cstdint>

#define Bb 4
#define Nn 4096
#define Dd 1024
#define Hh 16
#define DKk 64
#define Mm 256
#define TD 3072           // 3*D
#define Rr (Bb*Nn)        // 16384
#define BH (Bb*Hh)        // 64
#define SPLITS 8
#define EPSc 1e-6f

// ---------------- scratch (device globals; no cudaMalloc allowed) -----------
__device__ float g_qkv[(size_t)Rr*TD];            // 192 MB
__device__ float g_Qp[(size_t)BH*Nn*Mm];          // 64 MB
__device__ float g_Kp[(size_t)BH*Nn*Mm];          // 64 MB
__device__ float g_KVp[(size_t)BH*SPLITS*Mm*66];  // 34.6 MB (stride 66, aligned)
__device__ uint32_t g_KVth[(size_t)BH*80*128];    // KV^T hi (bf16x2 pairs)
__device__ uint32_t g_KVtl[(size_t)BH*80*128];    // KV^T lo
__device__ unsigned char g_mask[Rr];              // normalized pad mask (1 = PAD)
// pre-split bf16 pair buffers (pairs along k)
__device__ uint32_t g_xh[(size_t)Rr*Dd/2],  g_xl[(size_t)Rr*Dd/2];
__device__ uint32_t g_wqh[(size_t)TD*Dd/2], g_wql[(size_t)TD*Dd/2];
__device__ uint32_t g_woh[(size_t)Dd*Dd/2], g_wol[(size_t)Dd*Dd/2];
__device__ uint32_t g_cth[(size_t)Rr*Dd/2], g_ctl[(size_t)Rr*Dd/2];

// ---------------- bf16 split helpers ----------------------------------------
__device__ __forceinline__ uint32_t pkbf(float e0, float e1) {
    uint32_t r; asm("cvt.rn.bf16x2.f32 %0, %1, %2;" : "=r"(r) : "f"(e1), "f"(e0));
    return r;
}
__device__ __forceinline__ void split2(float v0, float v1, uint32_t& hp, uint32_t& lp) {
    hp = pkbf(v0, v1);
    float h0 = __uint_as_float(hp << 16);
    float h1 = __uint_as_float(hp & 0xFFFF0000u);
    lp = pkbf(v0 - h0, v1 - h1);
}
__device__ __forceinline__ void mma_bf16(float* c, uint32_t a0, uint32_t a1,
                                         uint32_t a2, uint32_t a3,
                                         uint32_t b0, uint32_t b1) {
    asm volatile(
        "mma.sync.aligned.m16n8k16.row.col.f32.bf16.bf16.f32 "
        "{%0,%1,%2,%3}, {%4,%5,%6,%7}, {%8,%9}, {%0,%1,%2,%3};"
        : "+f"(c[0]), "+f"(c[1]), "+f"(c[2]), "+f"(c[3])
        : "r"(a0), "r"(a1), "r"(a2), "r"(a3), "r"(b0), "r"(b1));
}
__device__ __forceinline__ uint32_t smem_u32(const void* p) {
    uint32_t a;
    asm("{ .reg .u64 t; cvta.to.shared.u64 t, %1; cvt.u32.u64 %0, t; }" : "=r"(a) : "l"(p));
    return a;
}
#define LDSM4(r0, r1, r2, r3, a) \
    asm volatile("ldmatrix.sync.aligned.m8n8.x4.shared.b16 {%0,%1,%2,%3}, [%4];" \
        : "=r"(r0), "=r"(r1), "=r"(r2), "=r"(r3) : "r"(a))

// ---------------- pre-split: float -> bf16 hi/lo pairs -----------------------
__global__ __launch_bounds__(256) void split_kernel(
    const float* __restrict__ src, uint32_t* __restrict__ h,
    uint32_t* __restrict__ l, int npairs)
{
    int i = blockIdx.x * blockDim.x + threadIdx.x;
    if (i >= npairs) return;
    float2 v = ((const float2*)src)[i];
    uint32_t hp, lp;
    split2(v.x, v.y, hp, lp);
    h[i] = hp; l[i] = lp;
}

// ================= 3x bf16 NT GEMM, pre-split inputs, ldmatrix ==============
#define MBM 128
#define MBN 128
#define PADU 20
#define SEC_AH 0
#define SEC_AL (128*PADU)
#define SEC_BH (2*128*PADU)
#define SEC_BL (3*128*PADU)
#define MG_BUF (4*128*PADU)
#define MG_SMEM (2*MG_BUF*4)           // 81920 bytes

__global__ __launch_bounds__(256) void mma_gemm_kernel(
    const uint32_t* __restrict__ Ah, const uint32_t* __restrict__ Al,
    const uint32_t* __restrict__ Wh, const uint32_t* __restrict__ Wl,
    const float* __restrict__ bias, float* __restrict__ C,
    int KP, int Ccols, const unsigned char* __restrict__ pad)
{
    extern __shared__ uint32_t smu[];
    uint32_t sb = smem_u32(smu);
    int tid = threadIdx.x, wid = tid >> 5, tl = tid & 31;
    int wm = wid & 1, wn = wid >> 1;
    int row0 = blockIdx.y * MBM, col0 = blockIdx.x * MBN;
    const uint32_t* Ahb = Ah + (size_t)row0 * KP;
    const uint32_t* Alb = Al + (size_t)row0 * KP;
    const uint32_t* Whb = Wh + (size_t)col0 * KP;
    const uint32_t* Wlb = Wl + (size_t)col0 * KP;
    int ar = tl >> 2, ac = tl & 3;

    int a_off = ((((tl >> 3) & 1) * 8 + (tl & 7)) * PADU + (tl >> 4) * 4);
    int b_off = ((((tl >> 4) & 1) * 8 + (tl & 7)) * PADU + ((tl >> 3) & 1) * 4);

    float acc[4][4][4];
    #pragma unroll
    for (int i = 0; i < 4; i++)
        #pragma unroll
        for (int j = 0; j < 4; j++)
            #pragma unroll
            for (int e = 0; e < 4; e++) acc[i][j][e] = 0.f;

    uint4 pa_h[2], pa_l[2], pb_h[2], pb_l[2];
    #pragma unroll
    for (int j = 0; j < 2; j++) {
        int idx = j*256 + tid;
        int row = idx >> 2, g = idx & 3;
        pa_h[j] = *(const uint4*)&Ahb[(size_t)row*KP + g*4];
        pa_l[j] = *(const uint4*)&Alb[(size_t)row*KP + g*4];
        pb_h[j] = *(const uint4*)&Whb[(size_t)row*KP + g*4];
        pb_l[j] = *(const uint4*)&Wlb[(size_t)row*KP + g*4];
    }

    const int NK = KP / 16;
    for (int i = 0; i < NK; i++) {
        uint32_t bufo = (uint32_t)(i & 1) * MG_BUF;
        uint32_t* buf = smu + bufo;
        #pragma unroll
        for (int j = 0; j < 2; j++) {
            int idx = j*256 + tid;
            int row = idx >> 2, g = idx & 3;
            int off = row*PADU + g*4;
            *(uint4*)&buf[SEC_AH + off] = pa_h[j];
            *(uint4*)&buf[SEC_AL + off] = pa_l[j];
            *(uint4*)&buf[SEC_BH + off] = pb_h[j];
            *(uint4*)&buf[SEC_BL + off] = pb_l[j];
        }
        if (i + 1 < NK) {
            int k0 = (i + 1) * 16;
            #pragma unroll
            for (int j = 0; j < 2; j++) {
                int idx = j*256 + tid;
                int row = idx >> 2, g = idx & 3;
                pa_h[j] = *(const uint4*)&Ahb[(size_t)row*KP + k0 + g*4];
                pa_l[j] = *(const uint4*)&Alb[(size_t)row*KP + k0 + g*4];
                pb_h[j] = *(const uint4*)&Whb[(size_t)row*KP + k0 + g*4];
                pb_l[j] = *(const uint4*)&Wlb[(size_t)row*KP + k0 + g*4];
            }
        }
        __syncthreads();
        #pragma unroll
        for (int s = 0; s < 2; s++) {
            int base = s * 8;
            uint32_t bhf[4][2], blf[4][2];
            #pragma unroll
            for (int p = 0; p < 2; p++) {
                uint32_t addr = sb + (bufo + SEC_BH + (uint32_t)(wn*32 + p*16)*PADU
                                      + base + b_off) * 4u;
                LDSM4(bhf[2*p][0], bhf[2*p][1], bhf[2*p+1][0], bhf[2*p+1][1], addr);
                addr += (SEC_BL - SEC_BH) * 4u;
                LDSM4(blf[2*p][0], blf[2*p][1], blf[2*p+1][0], blf[2*p+1][1], addr);
            }
            #pragma unroll
            for (int mi = 0; mi < 4; mi++) {
                uint32_t addr = sb + (bufo + SEC_AH + (uint32_t)(wm*64 + mi*16)*PADU
                                      + base + a_off) * 4u;
                uint32_t ah0, ah1, ah2, ah3, al0, al1, al2, al3;
                LDSM4(ah0, ah1, ah2, ah3, addr);
                addr += (SEC_AL - SEC_AH) * 4u;
                LDSM4(al0, al1, al2, al3, addr);
                #pragma unroll
                for (int ni = 0; ni < 4; ni++) {
                    mma_bf16(acc[mi][ni], ah0, ah1, ah2, ah3, bhf[ni][0], bhf[ni][1]);
                    mma_bf16(acc[mi][ni], ah0, ah1, ah2, ah3, blf[ni][0], blf[ni][1]);
                    mma_bf16(acc[mi][ni], al0, al1, al2, al3, bhf[ni][0], bhf[ni][1]);
                }
            }
        }
    }

    #pragma unroll
    for (int mi = 0; mi < 4; mi++) {
        int r0 = row0 + wm*64 + mi*16 + ar;
        float vm0 = 1.0f, vm1 = 1.0f;
        if (pad) { vm0 = pad[r0] ? 0.0f : 1.0f; vm1 = pad[r0+8] ? 0.0f : 1.0f; }
        #pragma unroll
        for (int ni = 0; ni < 4; ni++) {
            int c = col0 + wn*32 + ni*8 + ac*2;
            float b0 = bias[c], b1 = bias[c+1];
            *(float2*)&C[(size_t)r0 * Ccols + c] =
                make_float2((acc[mi][ni][0] + b0) * vm0, (acc[mi][ni][1] + b1) * vm0);
            *(float2*)&C[(size_t)(r0+8) * Ccols + c] =
                make_float2((acc[mi][ni][2] + b0) * vm1, (acc[mi][ni][3] + b1) * vm1);
        }
    }
}

// ---------------- mask dtype sniffing + normalization -----------------------
__global__ __launch_bounds__(1024) void normalize_mask_kernel(const unsigned char* raw)
{
    __shared__ int wide_bytes;
    const unsigned int* w = (const unsigned int*)raw;
    int t = threadIdx.x;
    if (t == 0) wide_bytes = 0;
    __syncthreads();
    int bad = 0;
    for (int i = t; i < Rr/4; i += 1024)
        if (w[i] > 1u) bad = 1;
    if (bad) atomicOr(&wide_bytes, 1);
    __syncthreads();
    if (wide_bytes) {
        for (int i = t; i < Rr; i += 1024) g_mask[i] = raw[i] ? 1 : 0;
    } else {
        for (int i = t; i < Rr; i += 1024) g_mask[i] = w[i] ? 1 : 0;
    }
}

// ---------------- fast exp (FMA-pipe) ---------------------------------------
__device__ __forceinline__ float fast_exp_neg(float z) {
    float y = z * 1.4426950408889634f;
    y = fmaxf(y, -125.0f);
    float t = y + 12582912.0f;
    int   i = __float_as_int(t) - 0x4B400000;
    float f = y - (t - 12582912.0f);
    float p = 1.5403530393381609e-4f;
    p = fmaf(p, f, 1.3333558146428443e-3f);
    p = fmaf(p, f, 9.618129107628477e-3f);
    p = fmaf(p, f, 5.550410866482158e-2f);
    p = fmaf(p, f, 2.402265069591007e-1f);
    p = fmaf(p, f, 6.931471805599453e-1f);
    p = fmaf(p, f, 1.0f);
    return __int_as_float(__float_as_int(p) + (i << 23));
}

// ================= phi via 3x bf16 mma: proj = t @ omega[h]^T ===============
// Block: 64 n-rows x 256 features, one (bh, q/k). K=64 (32 pairs).
// Warp grid 2m x 4n; warp tile 32 rows x 64 features.
#define PPAD 36
#define PB_AH 0
#define PB_AL (64*PPAD)
#define PB_BH (2*64*PPAD)
#define PB_BL (PB_BH + 256*PPAD)
#define PB_RM (PB_BH + 2*256*PPAD)
#define PHI_SMEM ((PB_RM + 64*4) * 4)       // 93,184 bytes

__global__ __launch_bounds__(256) void phi_mma_kernel(
    const float* __restrict__ qkv, const float* __restrict__ omega,
    const unsigned char* __restrict__ pad,
    float* __restrict__ Qp, float* __restrict__ Kp)
{
    extern __shared__ uint32_t smu[];
    float* smf = (float*)smu;
    int tid = threadIdx.x, wid = tid >> 5, tl = tid & 31;
    int wm = wid & 1, wn = wid >> 1;
    int ar = tl >> 2, ac = tl & 3;
    int bh = blockIdx.y; int b = bh >> 4, h = bh & 15;
    int qk = blockIdx.z;
    int n0 = blockIdx.x * 64;

    // A tile: 64 rows x 32 pairs (hi/lo)
    #pragma unroll
    for (int j = 0; j < 4; j++) {
        int idx = j*256 + tid;
        int row = idx >> 4, c4 = (idx & 15) * 4;
        const float* tp = qkv + (size_t)(b*Nn + n0 + row) * TD + qk * Dd + h * DKk;
        float4 v = *(const float4*)(tp + c4);
        uint32_t h0, l0, h1, l1;
        split2(v.x, v.y, h0, l0);
        split2(v.z, v.w, h1, l1);
        int off = row*PPAD + c4/2;
        *(uint2*)&smu[PB_AH + off] = make_uint2(h0, h1);
        *(uint2*)&smu[PB_AL + off] = make_uint2(l0, l1);
    }
    // B tile: omega[h], 256 rows x 32 pairs (hi/lo)
    #pragma unroll
    for (int j = 0; j < 16; j++) {
        int idx = j*256 + tid;
        int row = idx >> 4, c4 = (idx & 15) * 4;
        const float* op = omega + ((size_t)h * Mm + row) * DKk;
        float4 v = *(const float4*)(op + c4);
        uint32_t h0, l0, h1, l1;
        split2(v.x, v.y, h0, l0);
        split2(v.z, v.w, h1, l1);
        int off = row*PPAD + c4/2;
        *(uint2*)&smu[PB_BH + off] = make_uint2(h0, h1);
        *(uint2*)&smu[PB_BL + off] = make_uint2(l0, l1);
    }
    __syncthreads();

    float acc[2][8][4];
    #pragma unroll
    for (int i = 0; i < 2; i++)
        #pragma unroll
        for (int j = 0; j < 8; j++)
            #pragma unroll
            for (int e = 0; e < 4; e++) acc[i][j][e] = 0.f;

    #pragma unroll
    for (int sub = 0; sub < 4; sub++) {
        int base = sub * 8;
        uint32_t bhf[8][2], blf[8][2];
        #pragma unroll
        for (int ni = 0; ni < 8; ni++) {
            int n = wn*64 + ni*8 + ar;
            bhf[ni][0] = smu[PB_BH + n*PPAD + base + ac];
            bhf[ni][1] = smu[PB_BH + n*PPAD + base + 4 + ac];
            blf[ni][0] = smu[PB_BL + n*PPAD + base + ac];
            blf[ni][1] = smu[PB_BL + n*PPAD + base + 4 + ac];
        }
        #pragma unroll
        for (int mi = 0; mi < 2; mi++) {
            int m = wm*32 + mi*16 + ar;
            uint32_t ah0 = smu[PB_AH + m*PPAD + base + ac];
            uint32_t ah1 = smu[PB_AH + (m+8)*PPAD + base + ac];
            uint32_t ah2 = smu[PB_AH + m*PPAD + base + 4 + ac];
            uint32_t ah3 = smu[PB_AH + (m+8)*PPAD + base + 4 + ac];
            uint32_t al0 = smu[PB_AL + m*PPAD + base + ac];
            uint32_t al1 = smu[PB_AL + (m+8)*PPAD + base + ac];
            uint32_t al2 = smu[PB_AL + m*PPAD + base + 4 + ac];
            uint32_t al3 = smu[PB_AL + (m+8)*PPAD + base + 4 + ac];
            #pragma unroll
            for (int ni = 0; ni < 8; ni++) {
                mma_bf16(acc[mi][ni], ah0, ah1, ah2, ah3, bhf[ni][0], bhf[ni][1]);
                mma_bf16(acc[mi][ni], ah0, ah1, ah2, ah3, blf[ni][0], blf[ni][1]);
                mma_bf16(acc[mi][ni], al0, al1, al2, al3, bhf[ni][0], bhf[ni][1]);
            }
        }
    }

    // row max: per lane over 16 vals/row, shfl over ac-quad, smem across wn
    #pragma unroll
    for (int mi = 0; mi < 2; mi++) {
        float m0 = -1e30f, m1 = -1e30f;
        #pragma unroll
        for (int ni = 0; ni < 8; ni++) {
            m0 = fmaxf(m0, fmaxf(acc[mi][ni][0], acc[mi][ni][1]));
            m1 = fmaxf(m1, fmaxf(acc[mi][ni][2], acc[mi][ni][3]));
        }
        #pragma unroll
        for (int o = 1; o <= 2; o <<= 1) {
            m0 = fmaxf(m0, __shfl_xor_sync(0xffffffffu, m0, o));
            m1 = fmaxf(m1, __shfl_xor_sync(0xffffffffu, m1, o));
        }
        if (ac == 0) {
            int r = wm*32 + mi*16 + ar;
            smf[PB_RM + r*4 + wn] = m0;
            smf[PB_RM + (r+8)*4 + wn] = m1;
        }
    }
    __syncthreads();

    float* outp = qk ? Kp : Qp;
    #pragma unroll
    for (int mi = 0; mi < 2; mi++) {
        int r = wm*32 + mi*16 + ar;
        float mx0 = fmaxf(fmaxf(smf[PB_RM + r*4], smf[PB_RM + r*4+1]),
                          fmaxf(smf[PB_RM + r*4+2], smf[PB_RM + r*4+3]));
        float mx1 = fmaxf(fmaxf(smf[PB_RM + (r+8)*4], smf[PB_RM + (r+8)*4+1]),
                          fmaxf(smf[PB_RM + (r+8)*4+2], smf[PB_RM + (r+8)*4+3]));
        float s0 = 0.0625f, s1 = 0.0625f;
        if (qk) {
            if (pad[b*Nn + n0 + r]) s0 = 0.0f;
            if (pad[b*Nn + n0 + r + 8]) s1 = 0.0f;
        }
        float* d0 = outp + ((size_t)bh * Nn + n0 + r) * Mm;
        float* d1 = outp + ((size_t)bh * Nn + n0 + r + 8) * Mm;
        #pragma unroll
        for (int ni = 0; ni < 8; ni++) {
            int c = wn*64 + ni*8 + ac*2;
            *(float2*)(d0 + c) = make_float2(
                fast_exp_neg(acc[mi][ni][0] - mx0) * s0,
                fast_exp_neg(acc[mi][ni][1] - mx0) * s0);
            *(float2*)(d1 + c) = make_float2(
                fast_exp_neg(acc[mi][ni][2] - mx1) * s1,
                fast_exp_neg(acc[mi][ni][3] - mx1) * s1);
        }
    }
}

// ================= KV via 3x bf16 mma: KVp[m][d] = sum_n Kp[n,m] V[n,d] ====
// Per (bh, split): C = 256 m x 66 d (d=64 is ksum via ones column). k = n.
// 8 warps, each a 32-row m-tile; 9 n8 d-tiles (72 wide, store <= 65).
__global__ __launch_bounds__(256) void kv_mma_kernel(
    const float* __restrict__ Kp, const float* __restrict__ qkv,
    float* __restrict__ KVp)
{
    __shared__ float kps[32*260];
    __shared__ float vsm[32*76];
    int tid = threadIdx.x, wid = tid >> 5, tl = tid & 31;
    int ar = tl >> 2, ac = tl & 3;
    int s = blockIdx.x, bh = blockIdx.y;
    int b = bh >> 4, h = bh & 15;

    float acc[2][9][4];
    #pragma unroll
    for (int i = 0; i < 2; i++)
        #pragma unroll
        for (int j = 0; j < 9; j++)
            #pragma unroll
            for (int e = 0; e < 4; e++) acc[i][j][e] = 0.f;

    for (int n0 = s * (Nn/SPLITS); n0 < (s+1) * (Nn/SPLITS); n0 += 32) {
        __syncthreads();
        // Kp tile [32 n][256 m]
        #pragma unroll
        for (int j = 0; j < 8; j++) {
            int idx = j*256 + tid;
            int row = idx >> 6, c4 = (idx & 63) * 4;
            *(float4*)&kps[row*260 + c4] =
                *(const float4*)(Kp + ((size_t)bh*Nn + n0 + row)*Mm + c4);
        }
        // V tile [32 n][64 d] + cols 64..71 (64 = ones for ksum)
        #pragma unroll
        for (int j = 0; j < 2; j++) {
            int idx = j*256 + tid;
            int row = idx >> 4, g = (idx & 15) * 4;
            *(float4*)&vsm[row*76 + g] =
                *(const float4*)(qkv + (size_t)(b*Nn + n0 + row)*TD + 2*Dd + h*DKk + g);
        }
        {
            int row = tid >> 3, c = 64 + (tid & 7);
            vsm[row*76 + c] = (c == 64) ? 1.0f : 0.0f;
        }
        __syncthreads();
        #pragma unroll
        for (int sub = 0; sub < 2; sub++) {
            int kb = sub * 16;
            uint32_t bh_[9][2], bl_[9][2];
            #pragma unroll
            for (int ni = 0; ni < 9; ni++) {
                int d = ni*8 + ar;
                split2(vsm[(kb+2*ac)*76 + d],   vsm[(kb+2*ac+1)*76 + d],
                       bh_[ni][0], bl_[ni][0]);
                split2(vsm[(kb+2*ac+8)*76 + d], vsm[(kb+2*ac+9)*76 + d],
                       bh_[ni][1], bl_[ni][1]);
            }
            #pragma unroll
            for (int mi = 0; mi < 2; mi++) {
                int m = wid*32 + mi*16 + ar;
                uint32_t a0h,a0l,a1h,a1l,a2h,a2l,a3h,a3l;
                split2(kps[(kb+2*ac)*260 + m],     kps[(kb+2*ac+1)*260 + m],   a0h, a0l);
                split2(kps[(kb+2*ac)*260 + m+8],   kps[(kb+2*ac+1)*260 + m+8], a1h, a1l);
                split2(kps[(kb+2*ac+8)*260 + m],   kps[(kb+2*ac+9)*260 + m],   a2h, a2l);
                split2(kps[(kb+2*ac+8)*260 + m+8], kps[(kb+2*ac+9)*260 + m+8], a3h, a3l);
                #pragma unroll
                for (int ni = 0; ni < 9; ni++) {
                    mma_bf16(acc[mi][ni], a0h, a1h, a2h, a3h, bh_[ni][0], bh_[ni][1]);
                    mma_bf16(acc[mi][ni], a0h, a1h, a2h, a3h, bl_[ni][0], bl_[ni][1]);
                    mma_bf16(acc[mi][ni], a0l, a1l, a2l, a3l, bh_[ni][0], bh_[ni][1]);
                }
            }
        }
    }
    size_t base = ((size_t)(bh * SPLITS + s)) * Mm * 66;
    #pragma unroll
    for (int mi = 0; mi < 2; mi++) {
        int m0 = wid*32 + mi*16 + ar;
        #pragma unroll
        for (int ni = 0; ni < 9; ni++) {
            int d = ni*8 + 2*ac;
            if (ni < 8) {
                *(float2*)&KVp[base + (size_t)m0*66 + d] =
                    make_float2(acc[mi][ni][0], acc[mi][ni][1]);
                *(float2*)&KVp[base + (size_t)(m0+8)*66 + d] =
                    make_float2(acc[mi][ni][2], acc[mi][ni][3]);
            } else if (ac == 0) {
                KVp[base + (size_t)m0*66 + 64]     = acc[mi][ni][0];
                KVp[base + (size_t)(m0+8)*66 + 64] = acc[mi][ni][2];
            }
        }
    }
}

// --------- reduce splits + emit KV^T (80 x 128 bf16x2 pairs, hi/lo) ---------
__global__ void kvt_kernel(const float* __restrict__ KVp,
                           uint32_t* __restrict__ KVth, uint32_t* __restrict__ KVtl)
{
    int e = blockIdx.x * blockDim.x + threadIdx.x;
    if (e >= BH*80*128) return;
    int mp = e & 127; int rest = e >> 7; int d = rest % 80; int bh = rest / 80;
    float s0 = 0.f, s1 = 0.f;
    if (d < 65) {
        int m0 = mp * 2;
        const float* base = KVp + (size_t)bh * SPLITS * Mm * 66;
        #pragma unroll
        for (int sp = 0; sp < SPLITS; sp++) {
            s0 += base[(size_t)sp*Mm*66 + m0*66 + d];
            s1 += base[(size_t)sp*Mm*66 + (m0+1)*66 + d];
        }
    }
    uint32_t hp, lp;
    split2(s0, s1, hp, lp);
    KVth[e] = hp; KVtl[e] = lp;
}

// ---------------- ctx = (Qp@KV)/(Qp@ksum+eps), emits split bf16 pairs -------
#define CPAD 36
#define CT_AH 0
#define CT_AL (64*CPAD)
#define CT_BH (2*64*CPAD)
#define CT_BL (CT_BH + 80*CPAD)
#define CT_DEN (CT_BL + 80*CPAD)
#define CTX_SMEM ((CT_DEN + 64) * 4)

__global__ __launch_bounds__(256) void ctx_mma_kernel(
    const float* __restrict__ Qp, const uint32_t* __restrict__ KVth,
    const uint32_t* __restrict__ KVtl,
    uint32_t* __restrict__ cth, uint32_t* __restrict__ ctl)
{
    extern __shared__ uint32_t smu[];
    float* den_s = (float*)(smu + CT_DEN);
    int tid = threadIdx.x, wid = tid >> 5, tl = tid & 31;
    int wm = wid & 3, wn = wid >> 2;
    int ar = tl >> 2, ac = tl & 3;
    int bh = blockIdx.y; int b = bh >> 4, h = bh & 15;
    int n0 = blockIdx.x * 64;

    float acc[5][4];
    #pragma unroll
    for (int i = 0; i < 5; i++)
        #pragma unroll
        for (int e = 0; e < 4; e++) acc[i][e] = 0.f;

    for (int c = 0; c < 4; c++) {
        if (c) __syncthreads();
        #pragma unroll
        for (int j = 0; j < 4; j++) {
            int idx = j*256 + tid;
            int row = idx >> 4, f4 = idx & 15;
            float4 v = *(const float4*)(Qp + ((size_t)bh*Nn + n0 + row)*Mm + c*64 + f4*4);
            uint32_t h0, l0, h1, l1;
            split2(v.x, v.y, h0, l0);
            split2(v.z, v.w, h1, l1);
            int off = row*CPAD + f4*2;
            *(uint2*)&smu[CT_AH + off] = make_uint2(h0, h1);
            *(uint2*)&smu[CT_AL + off] = make_uint2(l0, l1);
        }
        #pragma unroll
        for (int j = 0; j < 3; j++) {
            int idx = j*256 + tid;
            if (idx < 640) {
                int row = idx >> 3, q4 = idx & 7;
                size_t src = ((size_t)bh*80 + row)*128 + c*32 + q4*4;
                *(uint4*)&smu[CT_BH + row*CPAD + q4*4] = *(const uint4*)&KVth[src];
                *(uint4*)&smu[CT_BL + row*CPAD + q4*4] = *(const uint4*)&KVtl[src];
            }
        }
        __syncthreads();
        #pragma unroll
        for (int s = 0; s < 4; s++) {
            int base = s * 8;
            int m = wm*16 + ar;
            uint32_t ah0 = smu[CT_AH + m*CPAD + base + ac];
            uint32_t ah1 = smu[CT_AH + (m+8)*CPAD + base + ac];
            uint32_t ah2 = smu[CT_AH + m*CPAD + base + 4 + ac];
            uint32_t ah3 = smu[CT_AH + (m+8)*CPAD + base + 4 + ac];
            uint32_t al0 = smu[CT_AL + m*CPAD + base + ac];
            uint32_t al1 = smu[CT_AL + (m+8)*CPAD + base + ac];
            uint32_t al2 = smu[CT_AL + m*CPAD + base + 4 + ac];
            uint32_t al3 = smu[CT_AL + (m+8)*CPAD + base + 4 + ac];
            #pragma unroll
            for (int ni = 0; ni < 5; ni++) {
                int n = wn*40 + ni*8 + ar;
                uint32_t b0h = smu[CT_BH + n*CPAD + base + ac];
                uint32_t b1h = smu[CT_BH + n*CPAD + base + 4 + ac];
                uint32_t b0l = smu[CT_BL + n*CPAD + base + ac];
                uint32_t b1l = smu[CT_BL + n*CPAD + base + 4 + ac];
                mma_bf16(acc[ni], ah0, ah1, ah2, ah3, b0h, b1h);
                mma_bf16(acc[ni], ah0, ah1, ah2, ah3, b0l, b1l);
                mma_bf16(acc[ni], al0, al1, al2, al3, b0h, b1h);
            }
        }
    }
    __syncthreads();
    if (wn == 1 && ac == 0) {
        int r = wm*16 + ar;
        den_s[r] = acc[3][0];
        den_s[r+8] = acc[3][2];
    }
    __syncthreads();

    int r = wm*16 + ar;
    float inv0 = 1.0f / (den_s[r] + EPSc);
    float inv1 = 1.0f / (den_s[r+8] + EPSc);
    size_t rb0 = (size_t)(b*Nn + n0 + r) * (Dd/2) + h*(DKk/2);
    size_t rb1 = (size_t)(b*Nn + n0 + r + 8) * (Dd/2) + h*(DKk/2);
    #pragma unroll
    for (int ni = 0; ni < 5; ni++) {
        int col = wn*40 + ni*8 + ac*2;
        if (col < 64) {
            uint32_t hp, lp;
            split2(acc[ni][0]*inv0, acc[ni][1]*inv0, hp, lp);
            cth[rb0 + (col>>1)] = hp; ctl[rb0 + (col>>1)] = lp;
            split2(acc[ni][2]*inv1, acc[ni][3]*inv1, hp, lp);
            cth[rb1 + (col>>1)] = hp; ctl[rb1 + (col>>1)] = lp;
        }
    }
}

// ---------------- launch ----------------------------------------------------
extern "C" void kernel_launch(void* const* d_in, const int* in_sizes, int n_in,
                              void* d_out, int out_size)
{
    const float *x = 0, *Wqkv = 0, *bqkv = 0, *Wout = 0, *bout = 0, *omega = 0;
    const unsigned char* mraw = 0;
    for (int i = 0; i < n_in; i++) {
        switch (in_sizes[i]) {
            case 16777216: x     = (const float*)d_in[i]; break;
            case 16384:    mraw  = (const unsigned char*)d_in[i]; break;
            case 3145728:  Wqkv  = (const float*)d_in[i]; break;
            case 3072:     bqkv  = (const float*)d_in[i]; break;
            case 1048576:  Wout  = (const float*)d_in[i]; break;
            case 1024:     bout  = (const float*)d_in[i]; break;
            case 262144:   omega = (const float*)d_in[i]; break;
            default: break;
        }
    }
    float* out = (float*)d_out;

    float *qkv, *Qp, *Kp, *KVp;
    uint32_t *KVth, *KVtl, *xh, *xl, *wqh, *wql, *woh, *wol, *cth, *ctl;
    unsigned char* mask;
    cudaGetSymbolAddress((void**)&qkv,  g_qkv);
    cudaGetSymbolAddress((void**)&Qp,   g_Qp);
    cudaGetSymbolAddress((void**)&Kp,   g_Kp);
    cudaGetSymbolAddress((void**)&KVp,  g_KVp);
    cudaGetSymbolAddress((void**)&KVth, g_KVth);
    cudaGetSymbolAddress((void**)&KVtl, g_KVtl);
    cudaGetSymbolAddress((void**)&mask, g_mask);
    cudaGetSymbolAddress((void**)&xh,   g_xh);
    cudaGetSymbolAddress((void**)&xl,   g_xl);
    cudaGetSymbolAddress((void**)&wqh,  g_wqh);
    cudaGetSymbolAddress((void**)&wql,  g_wql);
    cudaGetSymbolAddress((void**)&woh,  g_woh);
    cudaGetSymbolAddress((void**)&wol,  g_wol);
    cudaGetSymbolAddress((void**)&cth,  g_cth);
    cudaGetSymbolAddress((void**)&ctl,  g_ctl);

    cudaFuncSetAttribute(phi_mma_kernel, cudaFuncAttributeMaxDynamicSharedMemorySize, PHI_SMEM);
    cudaFuncSetAttribute(ctx_mma_kernel, cudaFuncAttributeMaxDynamicSharedMemorySize, CTX_SMEM);
    cudaFuncSetAttribute(mma_gemm_kernel, cudaFuncAttributeMaxDynamicSharedMemorySize, MG_SMEM);

    // 0) mask normalize + pre-split GEMM inputs
    normalize_mask_kernel<<<1, 1024>>>(mraw);
    split_kernel<<<(Rr*Dd/2 + 255)/256, 256>>>(x, xh, xl, Rr*Dd/2);
    split_kernel<<<(TD*Dd/2 + 255)/256, 256>>>(Wqkv, wqh, wql, TD*Dd/2);
    split_kernel<<<(Dd*Dd/2 + 255)/256, 256>>>(Wout, woh, wol, Dd*Dd/2);
    // 1) qkv = x @ Wqkv^T + bqkv   (3x bf16, pre-split, ldmatrix)
    mma_gemm_kernel<<<dim3(TD/MBN, Rr/MBM), 256, MG_SMEM>>>(
        xh, xl, wqh, wql, bqkv, qkv, Dd/2, TD, nullptr);
    // 2) Qp / Kp features (3x bf16 mma)
    phi_mma_kernel<<<dim3(Nn/64, BH, 2), 256, PHI_SMEM>>>(qkv, omega, mask, Qp, Kp);
    // 3) KV + ksum (3x bf16 mma split-K partials, then reduce into bf16 KV^T)
    kv_mma_kernel<<<dim3(SPLITS, BH), 256>>>(Kp, qkv, KVp);
    kvt_kernel<<<(BH*80*128 + 255)/256, 256>>>(KVp, KVth, KVtl);
    // 4) ctx (3x bf16 mma, den fused; emits pre-split bf16 ctx)
    ctx_mma_kernel<<<dim3(Nn/64, BH), 256, CTX_SMEM>>>(Qp, KVth, KVtl, cth, ctl);
    // 5) out = (ctx @ Wout^T + bout) * valid   (3x bf16, pre-split, ldmatrix)
    mma_gemm_kernel<<<dim3(Dd/MBN, Rr/MBM), 256, MG_SMEM>>>(
        cth, ctl, woh, wol, bout, out, Dd/2, Dd, mask);
}

// round 12
// speedup vs baseline: 1.0598x; 1.0598x over previous
#include <cuda_runtime.h>
#include <cuda_bf16.h>
#include <cuda_fp16.h>
#include <cstdint>

#define Bb 4
#define Nn 4096
#define Dd 1024
#define Hh 16
#define DKk 64
#define Mm 256
#define TD 3072           // 3*D
#define Rr (Bb*Nn)        // 16384
#define BH (Bb*Hh)        // 64
#define SPLITS 8
#define EPSc 1e-6f

// ---------------- scratch (device globals; no cudaMalloc allowed) -----------
__device__ float g_qkv[(size_t)Rr*TD];            // 192 MB
__device__ float g_Qp[(size_t)BH*Nn*Mm];          // 64 MB
__device__ float g_Kp[(size_t)BH*Nn*Mm];          // 64 MB
__device__ float g_KVp[(size_t)BH*SPLITS*Mm*66];  // 34.6 MB
__device__ uint32_t g_KVth[(size_t)BH*80*128];    // KV^T hi (bf16x2 pairs)
__device__ uint32_t g_KVtl[(size_t)BH*80*128];    // KV^T lo
__device__ unsigned char g_mask[Rr];              // normalized pad mask (1 = PAD)
// x in both formats (bf16 hi/lo for QK path, fp16 rounded for V path)
__device__ uint32_t g_xh[(size_t)Rr*Dd/2],  g_xl[(size_t)Rr*Dd/2];
__device__ uint32_t g_xf[(size_t)Rr*Dd/2];
// W buffers: Wq+Wk rows (bf16 split), Wv rows (fp16 split), Wout (fp16 split)
__device__ uint32_t g_wqh[(size_t)2048*Dd/2], g_wql[(size_t)2048*Dd/2];
__device__ uint32_t g_wvh[(size_t)Dd*Dd/2],  g_wvl[(size_t)Dd*Dd/2];
__device__ uint32_t g_woh[(size_t)Dd*Dd/2],  g_wol[(size_t)Dd*Dd/2];
__device__ uint32_t g_ctf[(size_t)Rr*Dd/2];       // ctx as fp16 pairs

// ---------------- pack/split helpers ----------------------------------------
__device__ __forceinline__ uint32_t pkbf(float e0, float e1) {
    uint32_t r; asm("cvt.rn.bf16x2.f32 %0, %1, %2;" : "=r"(r) : "f"(e1), "f"(e0));
    return r;
}
__device__ __forceinline__ void split2(float v0, float v1, uint32_t& hp, uint32_t& lp) {
    hp = pkbf(v0, v1);
    float h0 = __uint_as_float(hp << 16);
    float h1 = __uint_as_float(hp & 0xFFFF0000u);
    lp = pkbf(v0 - h0, v1 - h1);
}
__device__ __forceinline__ uint32_t pkf16(float e0, float e1) {
    uint32_t r; asm("cvt.rn.f16x2.f32 %0, %1, %2;" : "=r"(r) : "f"(e1), "f"(e0));
    return r;
}
__device__ __forceinline__ void split2f16(float v0, float v1, uint32_t& hp, uint32_t& lp) {
    hp = pkf16(v0, v1);
    __half2 hh = *reinterpret_cast<__half2*>(&hp);
    float2 hf = __half22float2(hh);
    lp = pkf16(v0 - hf.x, v1 - hf.y);
}
__device__ __forceinline__ void mma_bf16(float* c, uint32_t a0, uint32_t a1,
                                         uint32_t a2, uint32_t a3,
                                         uint32_t b0, uint32_t b1) {
    asm volatile(
        "mma.sync.aligned.m16n8k16.row.col.f32.bf16.bf16.f32 "
        "{%0,%1,%2,%3}, {%4,%5,%6,%7}, {%8,%9}, {%0,%1,%2,%3};"
        : "+f"(c[0]), "+f"(c[1]), "+f"(c[2]), "+f"(c[3])
        : "r"(a0), "r"(a1), "r"(a2), "r"(a3), "r"(b0), "r"(b1));
}
__device__ __forceinline__ void mma_f16(float* c, uint32_t a0, uint32_t a1,
                                        uint32_t a2, uint32_t a3,
                                        uint32_t b0, uint32_t b1) {
    asm volatile(
        "mma.sync.aligned.m16n8k16.row.col.f32.f16.f16.f32 "
        "{%0,%1,%2,%3}, {%4,%5,%6,%7}, {%8,%9}, {%0,%1,%2,%3};"
        : "+f"(c[0]), "+f"(c[1]), "+f"(c[2]), "+f"(c[3])
        : "r"(a0), "r"(a1), "r"(a2), "r"(a3), "r"(b0), "r"(b1));
}
__device__ __forceinline__ uint32_t smem_u32(const void* p) {
    uint32_t a;
    asm("{ .reg .u64 t; cvta.to.shared.u64 t, %1; cvt.u32.u64 %0, t; }" : "=r"(a) : "l"(p));
    return a;
}
#define LDSM4(r0, r1, r2, r3, a) \
    asm volatile("ldmatrix.sync.aligned.m8n8.x4.shared.b16 {%0,%1,%2,%3}, [%4];" \
        : "=r"(r0), "=r"(r1), "=r"(r2), "=r"(r3) : "r"(a))

// ---------------- pre-pass kernels -------------------------------------------
__global__ __launch_bounds__(256) void split_bf16_kernel(
    const float* __restrict__ src, uint32_t* __restrict__ h,
    uint32_t* __restrict__ l, int npairs)
{
    int i = blockIdx.x * blockDim.x + threadIdx.x;
    if (i >= npairs) return;
    float2 v = ((const float2*)src)[i];
    uint32_t hp, lp;
    split2(v.x, v.y, hp, lp);
    h[i] = hp; l[i] = lp;
}
__global__ __launch_bounds__(256) void round_f16_kernel(
    const float* __restrict__ src, uint32_t* __restrict__ h, int npairs)
{
    int i = blockIdx.x * blockDim.x + threadIdx.x;
    if (i >= npairs) return;
    float2 v = ((const float2*)src)[i];
    h[i] = pkf16(v.x, v.y);
}
__global__ __launch_bounds__(256) void split_f16_kernel(
    const float* __restrict__ src, uint32_t* __restrict__ h,
    uint32_t* __restrict__ l, int npairs)
{
    int i = blockIdx.x * blockDim.x + threadIdx.x;
    if (i >= npairs) return;
    float2 v = ((const float2*)src)[i];
    uint32_t hp, lp;
    split2f16(v.x, v.y, hp, lp);
    h[i] = hp; l[i] = lp;
}

// ====== 3-pass bf16 NT GEMM (pre-split A and W, ldmatrix) ===================
#define MBM 128
#define MBN 128
#define PADU 20
#define S3_AH 0
#define S3_AL (128*PADU)
#define S3_BH (2*128*PADU)
#define S3_BL (3*128*PADU)
#define MG3_BUF (4*128*PADU)
#define MG3_SMEM (2*MG3_BUF*4)          // 81920 bytes

__global__ __launch_bounds__(256) void gemm_bf3_kernel(
    const uint32_t* __restrict__ Ah, const uint32_t* __restrict__ Al,
    const uint32_t* __restrict__ Wh, const uint32_t* __restrict__ Wl,
    const float* __restrict__ bias, float* __restrict__ C,
    int KP, int Ccols, const unsigned char* __restrict__ pad)
{
    extern __shared__ uint32_t smu[];
    uint32_t sb = smem_u32(smu);
    int tid = threadIdx.x, wid = tid >> 5, tl = tid & 31;
    int wm = wid & 1, wn = wid >> 1;
    int row0 = blockIdx.y * MBM, col0 = blockIdx.x * MBN;
    const uint32_t* Ahb = Ah + (size_t)row0 * KP;
    const uint32_t* Alb = Al + (size_t)row0 * KP;
    const uint32_t* Whb = Wh + (size_t)col0 * KP;
    const uint32_t* Wlb = Wl + (size_t)col0 * KP;
    int ar = tl >> 2, ac = tl & 3;

    int a_off = ((((tl >> 3) & 1) * 8 + (tl & 7)) * PADU + (tl >> 4) * 4);
    int b_off = ((((tl >> 4) & 1) * 8 + (tl & 7)) * PADU + ((tl >> 3) & 1) * 4);

    float acc[4][4][4];
    #pragma unroll
    for (int i = 0; i < 4; i++)
        #pragma unroll
        for (int j = 0; j < 4; j++)
            #pragma unroll
            for (int e = 0; e < 4; e++) acc[i][j][e] = 0.f;

    uint4 pa_h[2], pa_l[2], pb_h[2], pb_l[2];
    #pragma unroll
    for (int j = 0; j < 2; j++) {
        int idx = j*256 + tid;
        int row = idx >> 2, g = idx & 3;
        pa_h[j] = *(const uint4*)&Ahb[(size_t)row*KP + g*4];
        pa_l[j] = *(const uint4*)&Alb[(size_t)row*KP + g*4];
        pb_h[j] = *(const uint4*)&Whb[(size_t)row*KP + g*4];
        pb_l[j] = *(const uint4*)&Wlb[(size_t)row*KP + g*4];
    }

    const int NK = KP / 16;
    for (int i = 0; i < NK; i++) {
        uint32_t bufo = (uint32_t)(i & 1) * MG3_BUF;
        uint32_t* buf = smu + bufo;
        #pragma unroll
        for (int j = 0; j < 2; j++) {
            int idx = j*256 + tid;
            int row = idx >> 2, g = idx & 3;
            int off = row*PADU + g*4;
            *(uint4*)&buf[S3_AH + off] = pa_h[j];
            *(uint4*)&buf[S3_AL + off] = pa_l[j];
            *(uint4*)&buf[S3_BH + off] = pb_h[j];
            *(uint4*)&buf[S3_BL + off] = pb_l[j];
        }
        if (i + 1 < NK) {
            int k0 = (i + 1) * 16;
            #pragma unroll
            for (int j = 0; j < 2; j++) {
                int idx = j*256 + tid;
                int row = idx >> 2, g = idx & 3;
                pa_h[j] = *(const uint4*)&Ahb[(size_t)row*KP + k0 + g*4];
                pa_l[j] = *(const uint4*)&Alb[(size_t)row*KP + k0 + g*4];
                pb_h[j] = *(const uint4*)&Whb[(size_t)row*KP + k0 + g*4];
                pb_l[j] = *(const uint4*)&Wlb[(size_t)row*KP + k0 + g*4];
            }
        }
        __syncthreads();
        #pragma unroll
        for (int s = 0; s < 2; s++) {
            int base = s * 8;
            uint32_t bhf[4][2], blf[4][2];
            #pragma unroll
            for (int p = 0; p < 2; p++) {
                uint32_t addr = sb + (bufo + S3_BH + (uint32_t)(wn*32 + p*16)*PADU
                                      + base + b_off) * 4u;
                LDSM4(bhf[2*p][0], bhf[2*p][1], bhf[2*p+1][0], bhf[2*p+1][1], addr);
                addr += (S3_BL - S3_BH) * 4u;
                LDSM4(blf[2*p][0], blf[2*p][1], blf[2*p+1][0], blf[2*p+1][1], addr);
            }
            #pragma unroll
            for (int mi = 0; mi < 4; mi++) {
                uint32_t addr = sb + (bufo + S3_AH + (uint32_t)(wm*64 + mi*16)*PADU
                                      + base + a_off) * 4u;
                uint32_t ah0, ah1, ah2, ah3, al0, al1, al2, al3;
                LDSM4(ah0, ah1, ah2, ah3, addr);
                addr += (S3_AL - S3_AH) * 4u;
                LDSM4(al0, al1, al2, al3, addr);
                #pragma unroll
                for (int ni = 0; ni < 4; ni++) {
                    mma_bf16(acc[mi][ni], ah0, ah1, ah2, ah3, bhf[ni][0], bhf[ni][1]);
                    mma_bf16(acc[mi][ni], ah0, ah1, ah2, ah3, blf[ni][0], blf[ni][1]);
                    mma_bf16(acc[mi][ni], al0, al1, al2, al3, bhf[ni][0], bhf[ni][1]);
                }
            }
        }
    }

    #pragma unroll
    for (int mi = 0; mi < 4; mi++) {
        int r0 = row0 + wm*64 + mi*16 + ar;
        float vm0 = 1.0f, vm1 = 1.0f;
        if (pad) { vm0 = pad[r0] ? 0.0f : 1.0f; vm1 = pad[r0+8] ? 0.0f : 1.0f; }
        #pragma unroll
        for (int ni = 0; ni < 4; ni++) {
            int c = col0 + wn*32 + ni*8 + ac*2;
            float b0 = bias[c], b1 = bias[c+1];
            *(float2*)&C[(size_t)r0 * Ccols + c] =
                make_float2((acc[mi][ni][0] + b0) * vm0, (acc[mi][ni][1] + b1) * vm0);
            *(float2*)&C[(size_t)(r0+8) * Ccols + c] =
                make_float2((acc[mi][ni][2] + b0) * vm1, (acc[mi][ni][3] + b1) * vm1);
        }
    }
}

// ====== 2-pass fp16 NT GEMM: C = fl16(A) @ (Wh+Wl)^T + bias, row mask =======
#define S2_A  0
#define S2_BH (128*PADU)
#define S2_BL (2*128*PADU)
#define MG2_BUF (3*128*PADU)
#define MG2_SMEM (2*MG2_BUF*4)          // 61440 bytes

__global__ __launch_bounds__(256) void gemm_f16_kernel(
    const uint32_t* __restrict__ Af,
    const uint32_t* __restrict__ Wh, const uint32_t* __restrict__ Wl,
    const float* __restrict__ bias, float* __restrict__ C,
    int KP, int Ccols, const unsigned char* __restrict__ pad)
{
    extern __shared__ uint32_t smu[];
    uint32_t sb = smem_u32(smu);
    int tid = threadIdx.x, wid = tid >> 5, tl = tid & 31;
    int wm = wid & 1, wn = wid >> 1;
    int row0 = blockIdx.y * MBM, col0 = blockIdx.x * MBN;
    const uint32_t* Afb = Af + (size_t)row0 * KP;
    const uint32_t* Whb = Wh + (size_t)col0 * KP;
    const uint32_t* Wlb = Wl + (size_t)col0 * KP;
    int ar = tl >> 2, ac = tl & 3;

    int a_off = ((((tl >> 3) & 1) * 8 + (tl & 7)) * PADU + (tl >> 4) * 4);
    int b_off = ((((tl >> 4) & 1) * 8 + (tl & 7)) * PADU + ((tl >> 3) & 1) * 4);

    float acc[4][4][4];
    #pragma unroll
    for (int i = 0; i < 4; i++)
        #pragma unroll
        for (int j = 0; j < 4; j++)
            #pragma unroll
            for (int e = 0; e < 4; e++) acc[i][j][e] = 0.f;

    uint4 pa[2], pbh[2], pbl[2];
    #pragma unroll
    for (int j = 0; j < 2; j++) {
        int idx = j*256 + tid;
        int row = idx >> 2, g = idx & 3;
        pa[j]  = *(const uint4*)&Afb[(size_t)row*KP + g*4];
        pbh[j] = *(const uint4*)&Whb[(size_t)row*KP + g*4];
        pbl[j] = *(const uint4*)&Wlb[(size_t)row*KP + g*4];
    }

    const int NK = KP / 16;
    for (int i = 0; i < NK; i++) {
        uint32_t bufo = (uint32_t)(i & 1) * MG2_BUF;
        uint32_t* buf = smu + bufo;
        #pragma unroll
        for (int j = 0; j < 2; j++) {
            int idx = j*256 + tid;
            int row = idx >> 2, g = idx & 3;
            int off = row*PADU + g*4;
            *(uint4*)&buf[S2_A  + off] = pa[j];
            *(uint4*)&buf[S2_BH + off] = pbh[j];
            *(uint4*)&buf[S2_BL + off] = pbl[j];
        }
        if (i + 1 < NK) {
            int k0 = (i + 1) * 16;
            #pragma unroll
            for (int j = 0; j < 2; j++) {
                int idx = j*256 + tid;
                int row = idx >> 2, g = idx & 3;
                pa[j]  = *(const uint4*)&Afb[(size_t)row*KP + k0 + g*4];
                pbh[j] = *(const uint4*)&Whb[(size_t)row*KP + k0 + g*4];
                pbl[j] = *(const uint4*)&Wlb[(size_t)row*KP + k0 + g*4];
            }
        }
        __syncthreads();
        #pragma unroll
        for (int s = 0; s < 2; s++) {
            int base = s * 8;
            uint32_t bhf[4][2], blf[4][2];
            #pragma unroll
            for (int p = 0; p < 2; p++) {
                uint32_t addr = sb + (bufo + S2_BH + (uint32_t)(wn*32 + p*16)*PADU
                                      + base + b_off) * 4u;
                LDSM4(bhf[2*p][0], bhf[2*p][1], bhf[2*p+1][0], bhf[2*p+1][1], addr);
                addr += (S2_BL - S2_BH) * 4u;
                LDSM4(blf[2*p][0], blf[2*p][1], blf[2*p+1][0], blf[2*p+1][1], addr);
            }
            #pragma unroll
            for (int mi = 0; mi < 4; mi++) {
                uint32_t addr = sb + (bufo + S2_A + (uint32_t)(wm*64 + mi*16)*PADU
                                      + base + a_off) * 4u;
                uint32_t a0, a1, a2, a3;
                LDSM4(a0, a1, a2, a3, addr);
                #pragma unroll
                for (int ni = 0; ni < 4; ni++) {
                    mma_f16(acc[mi][ni], a0, a1, a2, a3, bhf[ni][0], bhf[ni][1]);
                    mma_f16(acc[mi][ni], a0, a1, a2, a3, blf[ni][0], blf[ni][1]);
                }
            }
        }
    }

    #pragma unroll
    for (int mi = 0; mi < 4; mi++) {
        int r0 = row0 + wm*64 + mi*16 + ar;
        float vm0 = 1.0f, vm1 = 1.0f;
        if (pad) { vm0 = pad[r0] ? 0.0f : 1.0f; vm1 = pad[r0+8] ? 0.0f : 1.0f; }
        #pragma unroll
        for (int ni = 0; ni < 4; ni++) {
            int c = col0 + wn*32 + ni*8 + ac*2;
            float b0 = bias[c], b1 = bias[c+1];
            *(float2*)&C[(size_t)r0 * Ccols + c] =
                make_float2((acc[mi][ni][0] + b0) * vm0, (acc[mi][ni][1] + b1) * vm0);
            *(float2*)&C[(size_t)(r0+8) * Ccols + c] =
                make_float2((acc[mi][ni][2] + b0) * vm1, (acc[mi][ni][3] + b1) * vm1);
        }
    }
}

// ---------------- mask dtype sniffing + normalization -----------------------
__global__ __launch_bounds__(1024) void normalize_mask_kernel(const unsigned char* raw)
{
    __shared__ int wide_bytes;
    const unsigned int* w = (const unsigned int*)raw;
    int t = threadIdx.x;
    if (t == 0) wide_bytes = 0;
    __syncthreads();
    int bad = 0;
    for (int i = t; i < Rr/4; i += 1024)
        if (w[i] > 1u) bad = 1;
    if (bad) atomicOr(&wide_bytes, 1);
    __syncthreads();
    if (wide_bytes) {
        for (int i = t; i < Rr; i += 1024) g_mask[i] = raw[i] ? 1 : 0;
    } else {
        for (int i = t; i < Rr; i += 1024) g_mask[i] = w[i] ? 1 : 0;
    }
}

// ---------------- fast exp (FMA-pipe) ---------------------------------------
__device__ __forceinline__ float fast_exp_neg(float z) {
    float y = z * 1.4426950408889634f;
    y = fmaxf(y, -125.0f);
    float t = y + 12582912.0f;
    int   i = __float_as_int(t) - 0x4B400000;
    float f = y - (t - 12582912.0f);
    float p = 1.5403530393381609e-4f;
    p = fmaf(p, f, 1.3333558146428443e-3f);
    p = fmaf(p, f, 9.618129107628477e-3f);
    p = fmaf(p, f, 5.550410866482158e-2f);
    p = fmaf(p, f, 2.402265069591007e-1f);
    p = fmaf(p, f, 6.931471805599453e-1f);
    p = fmaf(p, f, 1.0f);
    return __int_as_float(__float_as_int(p) + (i << 23));
}

// ================= phi via 3x bf16 mma: proj = t @ omega[h]^T ===============
#define PPAD 36
#define PB_AH 0
#define PB_AL (64*PPAD)
#define PB_BH (2*64*PPAD)
#define PB_BL (PB_BH + 256*PPAD)
#define PB_RM (PB_BH + 2*256*PPAD)
#define PHI_SMEM ((PB_RM + 64*4) * 4)

__global__ __launch_bounds__(256) void phi_mma_kernel(
    const float* __restrict__ qkv, const float* __restrict__ omega,
    const unsigned char* __restrict__ pad,
    float* __restrict__ Qp, float* __restrict__ Kp)
{
    extern __shared__ uint32_t smu[];
    float* smf = (float*)smu;
    int tid = threadIdx.x, wid = tid >> 5, tl = tid & 31;
    int wm = wid & 1, wn = wid >> 1;
    int ar = tl >> 2, ac = tl & 3;
    int bh = blockIdx.y; int b = bh >> 4, h = bh & 15;
    int qk = blockIdx.z;
    int n0 = blockIdx.x * 64;

    #pragma unroll
    for (int j = 0; j < 4; j++) {
        int idx = j*256 + tid;
        int row = idx >> 4, c4 = (idx & 15) * 4;
        const float* tp = qkv + (size_t)(b*Nn + n0 + row) * TD + qk * Dd + h * DKk;
        float4 v = *(const float4*)(tp + c4);
        uint32_t h0, l0, h1, l1;
        split2(v.x, v.y, h0, l0);
        split2(v.z, v.w, h1, l1);
        int off = row*PPAD + c4/2;
        *(uint2*)&smu[PB_AH + off] = make_uint2(h0, h1);
        *(uint2*)&smu[PB_AL + off] = make_uint2(l0, l1);
    }
    #pragma unroll
    for (int j = 0; j < 16; j++) {
        int idx = j*256 + tid;
        int row = idx >> 4, c4 = (idx & 15) * 4;
        const float* op = omega + ((size_t)h * Mm + row) * DKk;
        float4 v = *(const float4*)(op + c4);
        uint32_t h0, l0, h1, l1;
        split2(v.x, v.y, h0, l0);
        split2(v.z, v.w, h1, l1);
        int off = row*PPAD + c4/2;
        *(uint2*)&smu[PB_BH + off] = make_uint2(h0, h1);
        *(uint2*)&smu[PB_BL + off] = make_uint2(l0, l1);
    }
    __syncthreads();

    float acc[2][8][4];
    #pragma unroll
    for (int i = 0; i < 2; i++)
        #pragma unroll
        for (int j = 0; j < 8; j++)
            #pragma unroll
            for (int e = 0; e < 4; e++) acc[i][j][e] = 0.f;

    #pragma unroll
    for (int sub = 0; sub < 4; sub++) {
        int base = sub * 8;
        uint32_t bhf[8][2], blf[8][2];
        #pragma unroll
        for (int ni = 0; ni < 8; ni++) {
            int n = wn*64 + ni*8 + ar;
            bhf[ni][0] = smu[PB_BH + n*PPAD + base + ac];
            bhf[ni][1] = smu[PB_BH + n*PPAD + base + 4 + ac];
            blf[ni][0] = smu[PB_BL + n*PPAD + base + ac];
            blf[ni][1] = smu[PB_BL + n*PPAD + base + 4 + ac];
        }
        #pragma unroll
        for (int mi = 0; mi < 2; mi++) {
            int m = wm*32 + mi*16 + ar;
            uint32_t ah0 = smu[PB_AH + m*PPAD + base + ac];
            uint32_t ah1 = smu[PB_AH + (m+8)*PPAD + base + ac];
            uint32_t ah2 = smu[PB_AH + m*PPAD + base + 4 + ac];
            uint32_t ah3 = smu[PB_AH + (m+8)*PPAD + base + 4 + ac];
            uint32_t al0 = smu[PB_AL + m*PPAD + base + ac];
            uint32_t al1 = smu[PB_AL + (m+8)*PPAD + base + ac];
            uint32_t al2 = smu[PB_AL + m*PPAD + base + 4 + ac];
            uint32_t al3 = smu[PB_AL + (m+8)*PPAD + base + 4 + ac];
            #pragma unroll
            for (int ni = 0; ni < 8; ni++) {
                mma_bf16(acc[mi][ni], ah0, ah1, ah2, ah3, bhf[ni][0], bhf[ni][1]);
                mma_bf16(acc[mi][ni], ah0, ah1, ah2, ah3, blf[ni][0], blf[ni][1]);
                mma_bf16(acc[mi][ni], al0, al1, al2, al3, bhf[ni][0], bhf[ni][1]);
            }
        }
    }

    #pragma unroll
    for (int mi = 0; mi < 2; mi++) {
        float m0 = -1e30f, m1 = -1e30f;
        #pragma unroll
        for (int ni = 0; ni < 8; ni++) {
            m0 = fmaxf(m0, fmaxf(acc[mi][ni][0], acc[mi][ni][1]));
            m1 = fmaxf(m1, fmaxf(acc[mi][ni][2], acc[mi][ni][3]));
        }
        #pragma unroll
        for (int o = 1; o <= 2; o <<= 1) {
            m0 = fmaxf(m0, __shfl_xor_sync(0xffffffffu, m0, o));
            m1 = fmaxf(m1, __shfl_xor_sync(0xffffffffu, m1, o));
        }
        if (ac == 0) {
            int r = wm*32 + mi*16 + ar;
            smf[PB_RM + r*4 + wn] = m0;
            smf[PB_RM + (r+8)*4 + wn] = m1;
        }
    }
    __syncthreads();

    float* outp = qk ? Kp : Qp;
    #pragma unroll
    for (int mi = 0; mi < 2; mi++) {
        int r = wm*32 + mi*16 + ar;
        float mx0 = fmaxf(fmaxf(smf[PB_RM + r*4], smf[PB_RM + r*4+1]),
                          fmaxf(smf[PB_RM + r*4+2], smf[PB_RM + r*4+3]));
        float mx1 = fmaxf(fmaxf(smf[PB_RM + (r+8)*4], smf[PB_RM + (r+8)*4+1]),
                          fmaxf(smf[PB_RM + (r+8)*4+2], smf[PB_RM + (r+8)*4+3]));
        float s0 = 0.0625f, s1 = 0.0625f;
        if (qk) {
            if (pad[b*Nn + n0 + r]) s0 = 0.0f;
            if (pad[b*Nn + n0 + r + 8]) s1 = 0.0f;
        }
        float* d0 = outp + ((size_t)bh * Nn + n0 + r) * Mm;
        float* d1 = outp + ((size_t)bh * Nn + n0 + r + 8) * Mm;
        #pragma unroll
        for (int ni = 0; ni < 8; ni++) {
            int c = wn*64 + ni*8 + ac*2;
            *(float2*)(d0 + c) = make_float2(
                fast_exp_neg(acc[mi][ni][0] - mx0) * s0,
                fast_exp_neg(acc[mi][ni][1] - mx0) * s0);
            *(float2*)(d1 + c) = make_float2(
                fast_exp_neg(acc[mi][ni][2] - mx1) * s1,
                fast_exp_neg(acc[mi][ni][3] - mx1) * s1);
        }
    }
}

// ================= KV via 3x bf16 mma: KVp[m][d] = sum_n Kp[n,m] V[n,d] ====
__global__ __launch_bounds__(256) void kv_mma_kernel(
    const float* __restrict__ Kp, const float* __restrict__ qkv,
    float* __restrict__ KVp)
{
    __shared__ float kps[32*260];
    __shared__ float vsm[32*76];
    int tid = threadIdx.x, wid = tid >> 5, tl = tid & 31;
    int ar = tl >> 2, ac = tl & 3;
    int s = blockIdx.x, bh = blockIdx.y;
    int b = bh >> 4, h = bh & 15;

    float acc[2][9][4];
    #pragma unroll
    for (int i = 0; i < 2; i++)
        #pragma unroll
        for (int j = 0; j < 9; j++)
            #pragma unroll
            for (int e = 0; e < 4; e++) acc[i][j][e] = 0.f;

    for (int n0 = s * (Nn/SPLITS); n0 < (s+1) * (Nn/SPLITS); n0 += 32) {
        __syncthreads();
        #pragma unroll
        for (int j = 0; j < 8; j++) {
            int idx = j*256 + tid;
            int row = idx >> 6, c4 = (idx & 63) * 4;
            *(float4*)&kps[row*260 + c4] =
                *(const float4*)(Kp + ((size_t)bh*Nn + n0 + row)*Mm + c4);
        }
        #pragma unroll
        for (int j = 0; j < 2; j++) {
            int idx = j*256 + tid;
            int row = idx >> 4, g = (idx & 15) * 4;
            *(float4*)&vsm[row*76 + g] =
                *(const float4*)(qkv + (size_t)(b*Nn + n0 + row)*TD + 2*Dd + h*DKk + g);
        }
        {
            int row = tid >> 3, c = 64 + (tid & 7);
            vsm[row*76 + c] = (c == 64) ? 1.0f : 0.0f;
        }
        __syncthreads();
        #pragma unroll
        for (int sub = 0; sub < 2; sub++) {
            int kb = sub * 16;
            uint32_t bh_[9][2], bl_[9][2];
            #pragma unroll
            for (int ni = 0; ni < 9; ni++) {
                int d = ni*8 + ar;
                split2(vsm[(kb+2*ac)*76 + d],   vsm[(kb+2*ac+1)*76 + d],
                       bh_[ni][0], bl_[ni][0]);
                split2(vsm[(kb+2*ac+8)*76 + d], vsm[(kb+2*ac+9)*76 + d],
                       bh_[ni][1], bl_[ni][1]);
            }
            #pragma unroll
            for (int mi = 0; mi < 2; mi++) {
                int m = wid*32 + mi*16 + ar;
                uint32_t a0h,a0l,a1h,a1l,a2h,a2l,a3h,a3l;
                split2(kps[(kb+2*ac)*260 + m],     kps[(kb+2*ac+1)*260 + m],   a0h, a0l);
                split2(kps[(kb+2*ac)*260 + m+8],   kps[(kb+2*ac+1)*260 + m+8], a1h, a1l);
                split2(kps[(kb+2*ac+8)*260 + m],   kps[(kb+2*ac+9)*260 + m],   a2h, a2l);
                split2(kps[(kb+2*ac+8)*260 + m+8], kps[(kb+2*ac+9)*260 + m+8], a3h, a3l);
                #pragma unroll
                for (int ni = 0; ni < 9; ni++) {
                    mma_bf16(acc[mi][ni], a0h, a1h, a2h, a3h, bh_[ni][0], bh_[ni][1]);
                    mma_bf16(acc[mi][ni], a0h, a1h, a2h, a3h, bl_[ni][0], bl_[ni][1]);
                    mma_bf16(acc[mi][ni], a0l, a1l, a2l, a3l, bh_[ni][0], bh_[ni][1]);
                }
            }
        }
    }
    size_t base = ((size_t)(bh * SPLITS + s)) * Mm * 66;
    #pragma unroll
    for (int mi = 0; mi < 2; mi++) {
        int m0 = wid*32 + mi*16 + ar;
        #pragma unroll
        for (int ni = 0; ni < 9; ni++) {
            int d = ni*8 + 2*ac;
            if (ni < 8) {
                *(float2*)&KVp[base + (size_t)m0*66 + d] =
                    make_float2(acc[mi][ni][0], acc[mi][ni][1]);
                *(float2*)&KVp[base + (size_t)(m0+8)*66 + d] =
                    make_float2(acc[mi][ni][2], acc[mi][ni][3]);
            } else if (ac == 0) {
                KVp[base + (size_t)m0*66 + 64]     = acc[mi][ni][0];
                KVp[base + (size_t)(m0+8)*66 + 64] = acc[mi][ni][2];
            }
        }
    }
}

// --------- reduce splits + emit KV^T (80 x 128 bf16x2 pairs, hi/lo) ---------
__global__ void kvt_kernel(const float* __restrict__ KVp,
                           uint32_t* __restrict__ KVth, uint32_t* __restrict__ KVtl)
{
    int e = blockIdx.x * blockDim.x + threadIdx.x;
    if (e >= BH*80*128) return;
    int mp = e & 127; int rest = e >> 7; int d = rest % 80; int bh = rest / 80;
    float s0 = 0.f, s1 = 0.f;
    if (d < 65) {
        int m0 = mp * 2;
        const float* base = KVp + (size_t)bh * SPLITS * Mm * 66;
        #pragma unroll
        for (int sp = 0; sp < SPLITS; sp++) {
            s0 += base[(size_t)sp*Mm*66 + m0*66 + d];
            s1 += base[(size_t)sp*Mm*66 + (m0+1)*66 + d];
        }
    }
    uint32_t hp, lp;
    split2(s0, s1, hp, lp);
    KVth[e] = hp; KVtl[e] = lp;
}

// ---------------- ctx = (Qp@KV)/(Qp@ksum+eps), emits fp16 pairs -------------
#define CPAD 36
#define CT_AH 0
#define CT_AL (64*CPAD)
#define CT_BH (2*64*CPAD)
#define CT_BL (CT_BH + 80*CPAD)
#define CT_DEN (CT_BL + 80*CPAD)
#define CTX_SMEM ((CT_DEN + 64) * 4)

__global__ __launch_bounds__(256) void ctx_mma_kernel(
    const float* __restrict__ Qp, const uint32_t* __restrict__ KVth,
    const uint32_t* __restrict__ KVtl, uint32_t* __restrict__ ctf)
{
    extern __shared__ uint32_t smu[];
    float* den_s = (float*)(smu + CT_DEN);
    int tid = threadIdx.x, wid = tid >> 5, tl = tid & 31;
    int wm = wid & 3, wn = wid >> 2;
    int ar = tl >> 2, ac = tl & 3;
    int bh = blockIdx.y; int b = bh >> 4, h = bh & 15;
    int n0 = blockIdx.x * 64;

    float acc[5][4];
    #pragma unroll
    for (int i = 0; i < 5; i++)
        #pragma unroll
        for (int e = 0; e < 4; e++) acc[i][e] = 0.f;

    for (int c = 0; c < 4; c++) {
        if (c) __syncthreads();
        #pragma unroll
        for (int j = 0; j < 4; j++) {
            int idx = j*256 + tid;
            int row = idx >> 4, f4 = idx & 15;
            float4 v = *(const float4*)(Qp + ((size_t)bh*Nn + n0 + row)*Mm + c*64 + f4*4);
            uint32_t h0, l0, h1, l1;
            split2(v.x, v.y, h0, l0);
            split2(v.z, v.w, h1, l1);
            int off = row*CPAD + f4*2;
            *(uint2*)&smu[CT_AH + off] = make_uint2(h0, h1);
            *(uint2*)&smu[CT_AL + off] = make_uint2(l0, l1);
        }
        #pragma unroll
        for (int j = 0; j < 3; j++) {
            int idx = j*256 + tid;
            if (idx < 640) {
                int row = idx >> 3, q4 = idx & 7;
                size_t src = ((size_t)bh*80 + row)*128 + c*32 + q4*4;
                *(uint4*)&smu[CT_BH + row*CPAD + q4*4] = *(const uint4*)&KVth[src];
                *(uint4*)&smu[CT_BL + row*CPAD + q4*4] = *(const uint4*)&KVtl[src];
            }
        }
        __syncthreads();
        #pragma unroll
        for (int s = 0; s < 4; s++) {
            int base = s * 8;
            int m = wm*16 + ar;
            uint32_t ah0 = smu[CT_AH + m*CPAD + base + ac];
            uint32_t ah1 = smu[CT_AH + (m+8)*CPAD + base + ac];
            uint32_t ah2 = smu[CT_AH + m*CPAD + base + 4 + ac];
            uint32_t ah3 = smu[CT_AH + (m+8)*CPAD + base + 4 + ac];
            uint32_t al0 = smu[CT_AL + m*CPAD + base + ac];
            uint32_t al1 = smu[CT_AL + (m+8)*CPAD + base + ac];
            uint32_t al2 = smu[CT_AL + m*CPAD + base + 4 + ac];
            uint32_t al3 = smu[CT_AL + (m+8)*CPAD + base + 4 + ac];
            #pragma unroll
            for (int ni = 0; ni < 5; ni++) {
                int n = wn*40 + ni*8 + ar;
                uint32_t b0h = smu[CT_BH + n*CPAD + base + ac];
                uint32_t b1h = smu[CT_BH + n*CPAD + base + 4 + ac];
                uint32_t b0l = smu[CT_BL + n*CPAD + base + ac];
                uint32_t b1l = smu[CT_BL + n*CPAD + base + 4 + ac];
                mma_bf16(acc[ni], ah0, ah1, ah2, ah3, b0h, b1h);
                mma_bf16(acc[ni], ah0, ah1, ah2, ah3, b0l, b1l);
                mma_bf16(acc[ni], al0, al1, al2, al3, b0h, b1h);
            }
        }
    }
    __syncthreads();
    if (wn == 1 && ac == 0) {
        int r = wm*16 + ar;
        den_s[r] = acc[3][0];
        den_s[r+8] = acc[3][2];
    }
    __syncthreads();

    int r = wm*16 + ar;
    float inv0 = 1.0f / (den_s[r] + EPSc);
    float inv1 = 1.0f / (den_s[r+8] + EPSc);
    size_t rb0 = (size_t)(b*Nn + n0 + r) * (Dd/2) + h*(DKk/2);
    size_t rb1 = (size_t)(b*Nn + n0 + r + 8) * (Dd/2) + h*(DKk/2);
    #pragma unroll
    for (int ni = 0; ni < 5; ni++) {
        int col = wn*40 + ni*8 + ac*2;
        if (col < 64) {
            ctf[rb0 + (col>>1)] = pkf16(acc[ni][0]*inv0, acc[ni][1]*inv0);
            ctf[rb1 + (col>>1)] = pkf16(acc[ni][2]*inv1, acc[ni][3]*inv1);
        }
    }
}

// ---------------- launch ----------------------------------------------------
extern "C" void kernel_launch(void* const* d_in, const int* in_sizes, int n_in,
                              void* d_out, int out_size)
{
    const float *x = 0, *Wqkv = 0, *bqkv = 0, *Wout = 0, *bout = 0, *omega = 0;
    const unsigned char* mraw = 0;
    for (int i = 0; i < n_in; i++) {
        switch (in_sizes[i]) {
            case 16777216: x     = (const float*)d_in[i]; break;
            case 16384:    mraw  = (const unsigned char*)d_in[i]; break;
            case 3145728:  Wqkv  = (const float*)d_in[i]; break;
            case 3072:     bqkv  = (const float*)d_in[i]; break;
            case 1048576:  Wout  = (const float*)d_in[i]; break;
            case 1024:     bout  = (const float*)d_in[i]; break;
            case 262144:   omega = (const float*)d_in[i]; break;
            default: break;
        }
    }
    float* out = (float*)d_out;

    float *qkv, *Qp, *Kp, *KVp;
    uint32_t *KVth, *KVtl, *xh, *xl, *xf, *wqh, *wql, *wvh, *wvl, *woh, *wol, *ctf;
    unsigned char* mask;
    cudaGetSymbolAddress((void**)&qkv,  g_qkv);
    cudaGetSymbolAddress((void**)&Qp,   g_Qp);
    cudaGetSymbolAddress((void**)&Kp,   g_Kp);
    cudaGetSymbolAddress((void**)&KVp,  g_KVp);
    cudaGetSymbolAddress((void**)&KVth, g_KVth);
    cudaGetSymbolAddress((void**)&KVtl, g_KVtl);
    cudaGetSymbolAddress((void**)&mask, g_mask);
    cudaGetSymbolAddress((void**)&xh,   g_xh);
    cudaGetSymbolAddress((void**)&xl,   g_xl);
    cudaGetSymbolAddress((void**)&xf,   g_xf);
    cudaGetSymbolAddress((void**)&wqh,  g_wqh);
    cudaGetSymbolAddress((void**)&wql,  g_wql);
    cudaGetSymbolAddress((void**)&wvh,  g_wvh);
    cudaGetSymbolAddress((void**)&wvl,  g_wvl);
    cudaGetSymbolAddress((void**)&woh,  g_woh);
    cudaGetSymbolAddress((void**)&wol,  g_wol);
    cudaGetSymbolAddress((void**)&ctf,  g_ctf);

    cudaFuncSetAttribute(phi_mma_kernel, cudaFuncAttributeMaxDynamicSharedMemorySize, PHI_SMEM);
    cudaFuncSetAttribute(ctx_mma_kernel, cudaFuncAttributeMaxDynamicSharedMemorySize, CTX_SMEM);
    cudaFuncSetAttribute(gemm_bf3_kernel, cudaFuncAttributeMaxDynamicSharedMemorySize, MG3_SMEM);
    cudaFuncSetAttribute(gemm_f16_kernel, cudaFuncAttributeMaxDynamicSharedMemorySize, MG2_SMEM);

    // 0) mask normalize + pre-pass conversions
    normalize_mask_kernel<<<1, 1024>>>(mraw);
    split_bf16_kernel<<<(Rr*Dd/2 + 255)/256, 256>>>(x, xh, xl, Rr*Dd/2);
    round_f16_kernel<<<(Rr*Dd/2 + 255)/256, 256>>>(x, xf, Rr*Dd/2);
    split_bf16_kernel<<<(2048*Dd/2 + 255)/256, 256>>>(Wqkv, wqh, wql, 2048*Dd/2);
    split_f16_kernel<<<(Dd*Dd/2 + 255)/256, 256>>>(Wqkv + (size_t)2048*Dd, wvh, wvl, Dd*Dd/2);
    split_f16_kernel<<<(Dd*Dd/2 + 255)/256, 256>>>(Wout, woh, wol, Dd*Dd/2);
    // 1a) Q,K columns: 3-pass bf16 (exp-critical precision)
    gemm_bf3_kernel<<<dim3(2048/MBN, Rr/MBM), 256, MG3_SMEM>>>(
        xh, xl, wqh, wql, bqkv, qkv, Dd/2, TD, nullptr);
    // 1b) V columns: 2-pass fp16 (linear error path)
    gemm_f16_kernel<<<dim3(Dd/MBN, Rr/MBM), 256, MG2_SMEM>>>(
        xf, wvh, wvl, bqkv + 2048, qkv + 2048, Dd/2, TD, nullptr);
    // 2) Qp / Kp features (3x bf16 mma)
    phi_mma_kernel<<<dim3(Nn/64, BH, 2), 256, PHI_SMEM>>>(qkv, omega, mask, Qp, Kp);
    // 3) KV + ksum (3x bf16 mma split-K, reduce into bf16 KV^T)
    kv_mma_kernel<<<dim3(SPLITS, BH), 256>>>(Kp, qkv, KVp);
    kvt_kernel<<<(BH*80*128 + 255)/256, 256>>>(KVp, KVth, KVtl);
    // 4) ctx (3x bf16 mma, den fused; emits fp16 ctx pairs)
    ctx_mma_kernel<<<dim3(Nn/64, BH), 256, CTX_SMEM>>>(Qp, KVth, KVtl, ctf);
    // 5) out = (ctx @ Wout^T + bout) * valid   (2-pass fp16)
    gemm_f16_kernel<<<dim3(Dd/MBN, Rr/MBM), 256, MG2_SMEM>>>(
        ctf, woh, wol, bout, out, Dd/2, Dd, mask);
}